// round 1
// baseline (speedup 1.0000x reference)
#include <cuda_runtime.h>
#include <cuda_bf16.h>

// Problem constants
#define BB 64
#define WW 128
#define FF 64
#define HH 2
#define OUTF 64
#define CH 128          // H*OUTF
#define TI 16           // destination tile per attention block
#define SSTRIDE 129     // fsrc smem row stride (odd -> conflict-free)

// Scratch: projected features (with bias)
__device__ float g_fsrc[BB * WW * CH];   // [b][w][h*64+f]
__device__ float g_fdst[BB * WW * CH];

// ---------------------------------------------------------------------------
// Kernel 1: projections. C[8192 x 256] = X[8192 x 64] @ W^T + bias
// grid (4, 128): blockIdx.x selects 64-output tile (0,1 -> src; 2,3 -> dst),
// blockIdx.y selects 64 rows of (b,w). 256 threads, 4x4 register tiles.
// ---------------------------------------------------------------------------
__global__ __launch_bounds__(256) void proj_kernel(
    const float* __restrict__ x,
    const float* __restrict__ w_src, const float* __restrict__ b_src,
    const float* __restrict__ w_dst, const float* __restrict__ b_dst)
{
    __shared__ float xs[64 * 65];
    __shared__ float ws[64 * 65];

    const int tid = threadIdx.x;
    const int ot = blockIdx.x;           // 0..3
    const int row0 = blockIdx.y * 64;    // bw row base
    const bool is_src = (ot < 2);
    const float* __restrict__ wm = is_src ? w_src : w_dst;
    const float* __restrict__ bv = is_src ? b_src : b_dst;
    const int obase = (ot & 1) * 64;     // local output channel base (0 or 64)

    // Fill smem tiles (padded stride 65 -> conflict-free compute reads)
    #pragma unroll
    for (int k = tid; k < 4096; k += 256) {
        int r = k >> 6, f = k & 63;
        xs[r * 65 + f] = x[(row0 + r) * FF + f];
    }
    #pragma unroll
    for (int k = tid; k < 4096; k += 256) {
        int o = k >> 6, f = k & 63;
        ws[o * 65 + f] = wm[(obase + o) * FF + f];
    }
    __syncthreads();

    const int cx = tid & 15;    // output sub-index
    const int ry = tid >> 4;    // row sub-index

    float acc[4][4];
    #pragma unroll
    for (int r = 0; r < 4; r++)
        #pragma unroll
        for (int c = 0; c < 4; c++) acc[r][c] = 0.0f;

    #pragma unroll 8
    for (int f = 0; f < 64; f++) {
        float xr[4], wv[4];
        #pragma unroll
        for (int r = 0; r < 4; r++) xr[r] = xs[(ry + 16 * r) * 65 + f];
        #pragma unroll
        for (int c = 0; c < 4; c++) wv[c] = ws[(cx + 16 * c) * 65 + f];
        #pragma unroll
        for (int r = 0; r < 4; r++)
            #pragma unroll
            for (int c = 0; c < 4; c++) acc[r][c] += xr[r] * wv[c];
    }

    float* __restrict__ dst = is_src ? g_fsrc : g_fdst;
    #pragma unroll
    for (int c = 0; c < 4; c++) {
        int oloc = obase + cx + 16 * c;       // channel 0..127
        float bias = bv[oloc];
        #pragma unroll
        for (int r = 0; r < 4; r++) {
            int bw = row0 + ry + 16 * r;
            dst[bw * CH + oloc] = acc[r][c] + bias;
        }
    }
}

// ---------------------------------------------------------------------------
// Kernel 2: attention. grid (8, 64): blockIdx.y = batch, blockIdx.x = i-tile.
// 256 threads. Whole fsrc[b] (128x128) resident in smem.
//   score:  e[i,j,h] = 1.5*(sA04[j,h] + dA04[i,h]) + sum_f (0.4 a_f)|s+d|
//   (leakyrelu(z) = 0.6 z + 0.4 |z| for slope 0.2)
//   softmax over j, fully in-warp (warp = (h, it) group, lanes = jt)
//   agg:    out[b,i,f] = 0.5 * sum_h sum_j alpha[i,j,h] * fsrc[j,h,f]
// ---------------------------------------------------------------------------
#define ATTN_SMEM_FLOATS (WW * SSTRIDE + TI * CH + 2 * TI * WW + CH + 2 * WW + 2 * TI)
#define ATTN_SMEM_BYTES (ATTN_SMEM_FLOATS * 4)

__global__ __launch_bounds__(256) void attn_kernel(
    const float* __restrict__ attn_w,
    float* __restrict__ out)
{
    extern __shared__ float sm[];
    float* fsrc_sm  = sm;                          // 128 * 129
    float* fdst_sm  = fsrc_sm + WW * SSTRIDE;      // 16 * 128
    float* alpha_sm = fdst_sm + TI * CH;           // 32 * 128  [h*16+i][j]
    float* attn04   = alpha_sm + 2 * TI * WW;      // 128 (0.4 * attn_w)
    float* sA       = attn04 + CH;                 // [h][128]  (0.4-scaled dots)
    float* dA       = sA + 2 * WW;                 // [h][16]

    const int tid = threadIdx.x;
    const int b = blockIdx.y;
    const int i0 = blockIdx.x * TI;

    // ---- load fsrc[b] (16384 floats) : float4 global reads, scalar smem stores
    const float* __restrict__ fsB = g_fsrc + b * WW * CH;
    #pragma unroll
    for (int k = tid; k < 4096; k += 256) {
        float4 v = *reinterpret_cast<const float4*>(fsB + k * 4);
        int j = (k * 4) >> 7;
        int ch = (k * 4) & 127;
        float* p = fsrc_sm + j * SSTRIDE + ch;
        p[0] = v.x; p[1] = v.y; p[2] = v.z; p[3] = v.w;
    }
    // ---- load fdst tile (16 x 128, contiguous)
    const float* __restrict__ fdB = g_fdst + (b * WW + i0) * CH;
    #pragma unroll
    for (int k = tid; k < 512; k += 256) {
        float4 v = *reinterpret_cast<const float4*>(fdB + k * 4);
        float* p = fdst_sm + k * 4;
        p[0] = v.x; p[1] = v.y; p[2] = v.z; p[3] = v.w;
    }
    if (tid < CH) attn04[tid] = 0.4f * attn_w[tid];
    __syncthreads();

    // ---- per-node attention dots with 0.4*a (linear leakyrelu component)
    {
        int h = tid >> 7, j = tid & 127;
        const float* ap = attn04 + h * 64;
        const float* sp = fsrc_sm + j * SSTRIDE + h * 64;
        float s = 0.0f;
        #pragma unroll
        for (int f = 0; f < 64; f++) s += ap[f] * sp[f];
        sA[h * WW + j] = s;
    }
    if (tid < 2 * TI) {
        int h = tid >> 4, il = tid & 15;
        const float* ap = attn04 + h * 64;
        const float* dp = fdst_sm + il * CH + h * 64;
        float s = 0.0f;
        #pragma unroll
        for (int f = 0; f < 64; f++) s += ap[f] * dp[f];
        dA[h * TI + il] = s;
    }
    __syncthreads();

    // ---- score phase: thread handles (h, it fixed), i = it+4r, j = jt+32c
    const int jt = tid & 31;
    const int it = (tid >> 5) & 3;
    const int h  = tid >> 7;

    float acc[4][4];
    #pragma unroll
    for (int r = 0; r < 4; r++)
        #pragma unroll
        for (int c = 0; c < 4; c++) acc[r][c] = 0.0f;

    {
        const float* ap = attn04 + h * 64;
        const float* dbase = fdst_sm + it * CH + h * 64;
        const float* sbase = fsrc_sm + jt * SSTRIDE + h * 64;
        #pragma unroll 8
        for (int f = 0; f < 64; f++) {
            float a = ap[f];
            float d0 = dbase[f];
            float d1 = dbase[4 * CH + f];
            float d2 = dbase[8 * CH + f];
            float d3 = dbase[12 * CH + f];
            float s0 = sbase[f];
            float s1 = sbase[32 * SSTRIDE + f];
            float s2 = sbase[64 * SSTRIDE + f];
            float s3 = sbase[96 * SSTRIDE + f];
            acc[0][0] += a * fabsf(s0 + d0);
            acc[0][1] += a * fabsf(s1 + d0);
            acc[0][2] += a * fabsf(s2 + d0);
            acc[0][3] += a * fabsf(s3 + d0);
            acc[1][0] += a * fabsf(s0 + d1);
            acc[1][1] += a * fabsf(s1 + d1);
            acc[1][2] += a * fabsf(s2 + d1);
            acc[1][3] += a * fabsf(s3 + d1);
            acc[2][0] += a * fabsf(s0 + d2);
            acc[2][1] += a * fabsf(s1 + d2);
            acc[2][2] += a * fabsf(s2 + d2);
            acc[2][3] += a * fabsf(s3 + d2);
            acc[3][0] += a * fabsf(s0 + d3);
            acc[3][1] += a * fabsf(s1 + d3);
            acc[3][2] += a * fabsf(s2 + d3);
            acc[3][3] += a * fabsf(s3 + d3);
        }
    }

    // ---- finalize scores + in-warp softmax (warp owns rows (h, it+4r))
    #pragma unroll
    for (int r = 0; r < 4; r++) {
        int il = it + 4 * r;
        float dv = dA[h * TI + il];
        float e[4];
        #pragma unroll
        for (int c = 0; c < 4; c++)
            e[c] = 1.5f * (sA[h * WW + jt + 32 * c] + dv) + acc[r][c];

        float m = fmaxf(fmaxf(e[0], e[1]), fmaxf(e[2], e[3]));
        #pragma unroll
        for (int off = 16; off > 0; off >>= 1)
            m = fmaxf(m, __shfl_xor_sync(0xffffffffu, m, off));

        float p[4], ssum = 0.0f;
        #pragma unroll
        for (int c = 0; c < 4; c++) { p[c] = __expf(e[c] - m); ssum += p[c]; }
        #pragma unroll
        for (int off = 16; off > 0; off >>= 1)
            ssum += __shfl_xor_sync(0xffffffffu, ssum, off);

        float inv = 1.0f / ssum;
        int row = h * TI + il;
        #pragma unroll
        for (int c = 0; c < 4; c++)
            alpha_sm[row * WW + jt + 32 * c] = p[c] * inv;
    }
    __syncthreads();

    // ---- aggregation: thread = (f = tid&63, rb = tid>>6); 4 i-rows, both heads
    {
        const int f = tid & 63;
        const int rb = tid >> 6;
        float a0[4], a1[4];
        #pragma unroll
        for (int k = 0; k < 4; k++) { a0[k] = 0.0f; a1[k] = 0.0f; }

        #pragma unroll 4
        for (int j = 0; j < WW; j++) {
            float s0 = fsrc_sm[j * SSTRIDE + f];
            float s1 = fsrc_sm[j * SSTRIDE + 64 + f];
            #pragma unroll
            for (int k = 0; k < 4; k++) {
                int il = rb + 4 * k;
                a0[k] += alpha_sm[il * WW + j] * s0;
                a1[k] += alpha_sm[(TI + il) * WW + j] * s1;
            }
        }
        #pragma unroll
        for (int k = 0; k < 4; k++) {
            int i = i0 + rb + 4 * k;
            out[(b * WW + i) * OUTF + f] = 0.5f * (a0[k] + a1[k]);
        }
    }
}

// ---------------------------------------------------------------------------
extern "C" void kernel_launch(void* const* d_in, const int* in_sizes, int n_in,
                              void* d_out, int out_size)
{
    (void)in_sizes; (void)n_in; (void)out_size;
    const float* x      = (const float*)d_in[0];
    const float* w_src  = (const float*)d_in[1];
    const float* b_src  = (const float*)d_in[2];
    const float* w_dst  = (const float*)d_in[3];
    const float* b_dst  = (const float*)d_in[4];
    const float* attn_w = (const float*)d_in[5];
    float* out = (float*)d_out;

    cudaFuncSetAttribute(attn_kernel,
                         cudaFuncAttributeMaxDynamicSharedMemorySize,
                         ATTN_SMEM_BYTES);

    proj_kernel<<<dim3(4, 128), 256>>>(x, w_src, b_src, w_dst, b_dst);
    attn_kernel<<<dim3(WW / TI, BB), 256, ATTN_SMEM_BYTES>>>(attn_w, out);
}

// round 2
// speedup vs baseline: 1.0455x; 1.0455x over previous
#include <cuda_runtime.h>

#define BB 64
#define WW 128
#define FF 64
#define OUTF 64
#define CH 128
#define TI 16

typedef unsigned long long ull;

// Scratch: projected features (with bias)
__device__ float g_fsrc[BB * WW * CH];
__device__ float g_fdst[BB * WW * CH];

// ---- packed f32x2 helpers ----
__device__ __forceinline__ ull fma2(ull a, ull b, ull c) {
    ull d; asm("fma.rn.f32x2 %0, %1, %2, %3;" : "=l"(d) : "l"(a), "l"(b), "l"(c)); return d;
}
__device__ __forceinline__ ull add2(ull a, ull b) {
    ull d; asm("add.rn.f32x2 %0, %1, %2;" : "=l"(d) : "l"(a), "l"(b)); return d;
}
__device__ __forceinline__ ull dup2(float a) {
    ull d; asm("mov.b64 %0, {%1, %1};" : "=l"(d) : "f"(a)); return d;
}
__device__ __forceinline__ float lo2(ull v) { return __uint_as_float((unsigned)(v & 0xffffffffu)); }
__device__ __forceinline__ float hi2(ull v) { return __uint_as_float((unsigned)(v >> 32)); }
__device__ __forceinline__ float hsum2(ull v) { return lo2(v) + hi2(v); }
#define ABSMASK 0x7fffffff7fffffffULL

// 16B-chunk swizzle within a 128-float row (32 chunks): permute low 3 bits by row
__device__ __forceinline__ int swz(int row, int c) { return (c & 24) | ((c ^ row) & 7); }

// ---------------------------------------------------------------------------
// Kernel 1: projections. C[8192 x 256] = X[8192 x 64] @ W^T + bias
// grid (4, 128), 256 threads, float4 smem, f32x2 packed accumulation.
// ---------------------------------------------------------------------------
__global__ __launch_bounds__(256) void proj_kernel(
    const float* __restrict__ x,
    const float* __restrict__ w_src, const float* __restrict__ b_src,
    const float* __restrict__ w_dst, const float* __restrict__ b_dst)
{
    __shared__ float xs[64 * 68];   // padded: row stride 68 floats = 17 chunks (16B)
    __shared__ float ws[64 * 68];

    const int tid = threadIdx.x;
    const int ot = blockIdx.x;           // 0..3
    const int row0 = blockIdx.y * 64;
    const bool is_src = (ot < 2);
    const float* __restrict__ wm = is_src ? w_src : w_dst;
    const float* __restrict__ bv = is_src ? b_src : b_dst;
    const int obase = (ot & 1) * 64;

    const float4* __restrict__ x4 = (const float4*)(x + row0 * FF);
    const float4* __restrict__ w4 = (const float4*)(wm + obase * FF);
    #pragma unroll
    for (int t = 0; t < 4; t++) {
        int m = tid + 256 * t;          // 1024 float4 per tile
        int r = m >> 4, c4 = m & 15;
        *(float4*)(xs + r * 68 + c4 * 4) = x4[m];
        *(float4*)(ws + r * 68 + c4 * 4) = w4[m];
    }
    __syncthreads();

    const int cx = tid & 15;
    const int ry = tid >> 4;

    ull acc[4][4];
    #pragma unroll
    for (int r = 0; r < 4; r++)
        #pragma unroll
        for (int c = 0; c < 4; c++) acc[r][c] = 0ULL;

    const ulonglong2* __restrict__ xs16 = (const ulonglong2*)xs;
    const ulonglong2* __restrict__ ws16 = (const ulonglong2*)ws;

    #pragma unroll 4
    for (int f4 = 0; f4 < 16; f4++) {
        ulonglong2 xr[4], wv[4];
        #pragma unroll
        for (int r = 0; r < 4; r++) xr[r] = xs16[(ry + 16 * r) * 17 + f4];
        #pragma unroll
        for (int c = 0; c < 4; c++) wv[c] = ws16[(cx + 16 * c) * 17 + f4];
        #pragma unroll
        for (int r = 0; r < 4; r++)
            #pragma unroll
            for (int c = 0; c < 4; c++) {
                acc[r][c] = fma2(xr[r].x, wv[c].x, acc[r][c]);
                acc[r][c] = fma2(xr[r].y, wv[c].y, acc[r][c]);
            }
    }

    float* __restrict__ dst = is_src ? g_fsrc : g_fdst;
    #pragma unroll
    for (int c = 0; c < 4; c++) {
        int oloc = obase + cx + 16 * c;
        float bias = bv[oloc];
        #pragma unroll
        for (int r = 0; r < 4; r++) {
            int bw = row0 + ry + 16 * r;
            dst[bw * CH + oloc] = hsum2(acc[r][c]) + bias;
        }
    }
}

// ---------------------------------------------------------------------------
// Kernel 2: attention. grid (8, 64), 256 threads.
// smem layout (floats):
//   fsrc   [128 x 128]   swizzled 16B chunks           0 .. 16384
//   fdst   [16 x 128]                               16384 .. 18432
//   alpha2 [32 rows x 128 j] of DUPLICATED f32 pairs 18432 .. 26624
//   a04    [128]                                    26624 .. 26752
//   sA     [2 x 128]                                26752 .. 27008
//   dA     [2 x 16]                                 27008 .. 27040
// ---------------------------------------------------------------------------
#define OFF_FDST  (WW * CH)
#define OFF_ALPHA (OFF_FDST + TI * CH)
#define OFF_A04   (OFF_ALPHA + 2 * TI * WW * 2)
#define OFF_SA    (OFF_A04 + CH)
#define OFF_DA    (OFF_SA + 2 * WW)
#define SM_FLOATS (OFF_DA + 2 * TI)
#define SM_BYTES  (SM_FLOATS * 4)

__global__ __launch_bounds__(256, 2) void attn_kernel(
    const float* __restrict__ attn_w,
    float* __restrict__ out)
{
    extern __shared__ float sm[];
    float* fsrc_sm = sm;
    float* fdst_sm = sm + OFF_FDST;
    ull*   alpha2  = (ull*)(sm + OFF_ALPHA);
    float* a04     = sm + OFF_A04;
    float* sA      = sm + OFF_SA;
    float* dA      = sm + OFF_DA;

    const int tid = threadIdx.x;
    const int b = blockIdx.y;
    const int i0 = blockIdx.x * TI;

    // ---- fill fsrc (swizzled, STS.128) ----
    const ulonglong2* __restrict__ gs16 = (const ulonglong2*)(g_fsrc + b * WW * CH);
    ulonglong2* fs16 = (ulonglong2*)fsrc_sm;
    #pragma unroll
    for (int t = 0; t < 16; t++) {
        int m = tid + 256 * t;           // 4096 chunks
        int j = m >> 5, c = m & 31;
        fs16[j * 32 + swz(j, c)] = gs16[m];
    }
    // ---- fill fdst tile (contiguous) ----
    {
        const float4* __restrict__ gd4 = (const float4*)(g_fdst + (b * WW + i0) * CH);
        float4* fd4 = (float4*)fdst_sm;
        fd4[tid] = gd4[tid];
        fd4[tid + 256] = gd4[tid + 256];
    }
    if (tid < CH) a04[tid] = 0.4f * attn_w[tid];
    __syncthreads();

    // ---- per-node dots with 0.4*a (linear leakyrelu component) ----
    {
        int h = tid >> 7, j = tid & 127;
        const ulonglong2* a16 = (const ulonglong2*)a04;
        ull acc = 0ULL;
        #pragma unroll
        for (int f4 = 0; f4 < 16; f4++) {
            int c = h * 16 + f4;
            ulonglong2 sv = fs16[j * 32 + swz(j, c)];
            ulonglong2 av = a16[h * 16 + f4];
            acc = fma2(av.x, sv.x, acc);
            acc = fma2(av.y, sv.y, acc);
        }
        sA[h * WW + j] = hsum2(acc);
    }
    if (tid < 2 * TI) {
        int h = tid >> 4, il = tid & 15;
        const ulonglong2* d16 = (const ulonglong2*)fdst_sm;
        const ulonglong2* a16 = (const ulonglong2*)a04;
        ull acc = 0ULL;
        #pragma unroll
        for (int f4 = 0; f4 < 16; f4++) {
            ulonglong2 dv = d16[il * 32 + h * 16 + f4];
            ulonglong2 av = a16[h * 16 + f4];
            acc = fma2(av.x, dv.x, acc);
            acc = fma2(av.y, dv.y, acc);
        }
        dA[tid] = hsum2(acc);        // dA[h*16 + il]
    }
    __syncthreads();

    // ---- score phase: warp = (h, it); lanes = jt; i = it+4r, j = jt+32c ----
    const int jt = tid & 31;
    const int it = (tid >> 5) & 3;
    const int h  = tid >> 7;

    ull acc2[4][4];
    #pragma unroll
    for (int r = 0; r < 4; r++)
        #pragma unroll
        for (int c = 0; c < 4; c++) acc2[r][c] = 0ULL;

    {
        const ulonglong2* a16 = (const ulonglong2*)a04 + h * 16;
        const ulonglong2* d16 = (const ulonglong2*)fdst_sm;
        #pragma unroll 4
        for (int f4 = 0; f4 < 16; f4++) {
            ulonglong2 av = a16[f4];
            ulonglong2 dv[4], sv[4];
            #pragma unroll
            for (int r = 0; r < 4; r++)
                dv[r] = d16[(it + 4 * r) * 32 + h * 16 + f4];
            int cs = swz(jt, h * 16 + f4);
            #pragma unroll
            for (int c = 0; c < 4; c++)
                sv[c] = fs16[(jt + 32 * c) * 32 + cs];
            #pragma unroll
            for (int r = 0; r < 4; r++)
                #pragma unroll
                for (int c = 0; c < 4; c++) {
                    ull t0 = add2(sv[c].x, dv[r].x) & ABSMASK;
                    acc2[r][c] = fma2(av.x, t0, acc2[r][c]);
                    ull t1 = add2(sv[c].y, dv[r].y) & ABSMASK;
                    acc2[r][c] = fma2(av.y, t1, acc2[r][c]);
                }
        }
    }

    // ---- softmax (fully in-warp over j), write DUPLICATED alpha pairs ----
    {
        float sAv[4];
        #pragma unroll
        for (int c = 0; c < 4; c++) sAv[c] = sA[h * WW + jt + 32 * c];

        #pragma unroll
        for (int r = 0; r < 4; r++) {
            int il = it + 4 * r;
            float dv = dA[h * TI + il];
            float e[4];
            #pragma unroll
            for (int c = 0; c < 4; c++)
                e[c] = 1.5f * (sAv[c] + dv) + hsum2(acc2[r][c]);

            float m = fmaxf(fmaxf(e[0], e[1]), fmaxf(e[2], e[3]));
            #pragma unroll
            for (int off = 16; off > 0; off >>= 1)
                m = fmaxf(m, __shfl_xor_sync(0xffffffffu, m, off));

            float p[4], ssum = 0.0f;
            #pragma unroll
            for (int c = 0; c < 4; c++) { p[c] = __expf(e[c] - m); ssum += p[c]; }
            #pragma unroll
            for (int off = 16; off > 0; off >>= 1)
                ssum += __shfl_xor_sync(0xffffffffu, ssum, off);

            float inv = 1.0f / ssum;
            int row = h * TI + il;
            #pragma unroll
            for (int c = 0; c < 4; c++)
                alpha2[row * WW + jt + 32 * c] = dup2(p[c] * inv);
        }
    }
    __syncthreads();

    // ---- aggregation: jh = j-half, r4 selects i-rows {r4+4k}, f2 = float-pair
    const int jh = tid >> 7;
    const int r4 = (tid >> 5) & 3;
    const int f2 = tid & 31;

    ull accA0[4], accA1[4];
    #pragma unroll
    for (int k = 0; k < 4; k++) { accA0[k] = 0ULL; accA1[k] = 0ULL; }

    {
        const ulonglong2* A2 = (const ulonglong2*)alpha2;   // [row][64 pairs of j]
        const ull* fs8 = (const ull*)fsrc_sm;               // 8B units
        const int c0 = f2 >> 1;
        const int half = f2 & 1;

        #pragma unroll 4
        for (int jp = 0; jp < 32; jp++) {                   // pairs of j in my half
            int jp2 = jh * 32 + jp;
            int j0 = 2 * jp2;
            int j1 = j0 + 1;
            ulonglong2 al0[4], al1[4];
            #pragma unroll
            for (int k = 0; k < 4; k++) {
                al0[k] = A2[(r4 + 4 * k) * 64 + jp2];        // head0 rows
                al1[k] = A2[(TI + r4 + 4 * k) * 64 + jp2];   // head1 rows
            }
            int b0 = j0 * 64 + swz(j0, c0) * 2 + half;
            int b1 = j1 * 64 + swz(j1, c0) * 2 + half;
            ull s00 = fs8[b0];          // head0, j0
            ull s01 = fs8[b0 + 32];     // head1 (chunk +16 = +32 ull)
            ull s10 = fs8[b1];          // head0, j1
            ull s11 = fs8[b1 + 32];     // head1, j1
            #pragma unroll
            for (int k = 0; k < 4; k++) {
                accA0[k] = fma2(al0[k].x, s00, accA0[k]);
                accA0[k] = fma2(al0[k].y, s10, accA0[k]);
                accA1[k] = fma2(al1[k].x, s01, accA1[k]);
                accA1[k] = fma2(al1[k].y, s11, accA1[k]);
            }
        }
    }

    // ---- cross-half reduction + write ----
    __syncthreads();                        // everyone done reading alpha/fsrc
    {
        ull* red = (ull*)fdst_sm;           // scratch (9-ull stride, spills into dead alpha)
        if (jh == 1) {
            int base = (tid & 127) * 9;
            #pragma unroll
            for (int k = 0; k < 4; k++) {
                red[base + k] = accA0[k];
                red[base + 4 + k] = accA1[k];
            }
        }
        __syncthreads();
        if (jh == 0) {
            const ull* rr = red + tid * 9;
            #pragma unroll
            for (int k = 0; k < 4; k++) {
                ull h0 = add2(accA0[k], rr[k]);
                ull h1 = add2(accA1[k], rr[4 + k]);
                ull s = add2(h0, h1);
                int il = r4 + 4 * k;
                float2 o;
                o.x = 0.5f * lo2(s);
                o.y = 0.5f * hi2(s);
                *(float2*)(out + (b * WW + i0 + il) * OUTF + f2 * 2) = o;
            }
        }
    }
}

// ---------------------------------------------------------------------------
extern "C" void kernel_launch(void* const* d_in, const int* in_sizes, int n_in,
                              void* d_out, int out_size)
{
    (void)in_sizes; (void)n_in; (void)out_size;
    const float* x      = (const float*)d_in[0];
    const float* w_src  = (const float*)d_in[1];
    const float* b_src  = (const float*)d_in[2];
    const float* w_dst  = (const float*)d_in[3];
    const float* b_dst  = (const float*)d_in[4];
    const float* attn_w = (const float*)d_in[5];
    float* out = (float*)d_out;

    cudaFuncSetAttribute(attn_kernel,
                         cudaFuncAttributeMaxDynamicSharedMemorySize,
                         SM_BYTES);

    proj_kernel<<<dim3(4, 128), 256>>>(x, w_src, b_src, w_dst, b_dst);
    attn_kernel<<<dim3(WW / TI, BB), 256, SM_BYTES>>>(attn_w, out);
}

// round 3
// speedup vs baseline: 1.1800x; 1.1287x over previous
#include <cuda_runtime.h>

#define BB 64
#define WW 128
#define FF 64
#define OUTF 64
#define CH 128
#define TI 16

typedef unsigned long long ull;

// Scratch: projected features (with bias)
__device__ float g_fsrc[BB * WW * CH];
__device__ float g_fdst[BB * WW * CH];

// ---- packed f32x2 helpers ----
__device__ __forceinline__ ull fma2(ull a, ull b, ull c) {
    ull d; asm("fma.rn.f32x2 %0, %1, %2, %3;" : "=l"(d) : "l"(a), "l"(b), "l"(c)); return d;
}
__device__ __forceinline__ ull add2(ull a, ull b) {
    ull d; asm("add.rn.f32x2 %0, %1, %2;" : "=l"(d) : "l"(a), "l"(b)); return d;
}
__device__ __forceinline__ ull dup2(float a) {
    ull d; asm("mov.b64 %0, {%1, %1};" : "=l"(d) : "f"(a)); return d;
}
__device__ __forceinline__ float lo2(ull v) { return __uint_as_float((unsigned)(v & 0xffffffffu)); }
__device__ __forceinline__ float hi2(ull v) { return __uint_as_float((unsigned)(v >> 32)); }
__device__ __forceinline__ float hsum2(ull v) { return lo2(v) + hi2(v); }
#define ABSMASK 0x7fffffff7fffffffULL

// 16B-chunk swizzle within a 64-float (16-chunk) row
__device__ __forceinline__ int swz16(int row, int c) { return (c & 8) | ((c ^ row) & 7); }

// ---------------------------------------------------------------------------
// Kernel 1: projections + zero-init of out.
// C[8192 x 256] = X[8192 x 64] @ W^T + bias. grid (4, 128), 256 threads.
// ---------------------------------------------------------------------------
__global__ __launch_bounds__(256) void proj_kernel(
    const float* __restrict__ x,
    const float* __restrict__ w_src, const float* __restrict__ b_src,
    const float* __restrict__ w_dst, const float* __restrict__ b_dst,
    float* __restrict__ out)
{
    __shared__ float xs[64 * 68];
    __shared__ float ws[64 * 68];

    const int tid = threadIdx.x;
    const int ot = blockIdx.x;           // 0..3
    const int row0 = blockIdx.y * 64;
    const bool is_src = (ot < 2);
    const float* __restrict__ wm = is_src ? w_src : w_dst;
    const float* __restrict__ bv = is_src ? b_src : b_dst;
    const int obase = (ot & 1) * 64;

    // zero-init out (512 blocks x 256 threads x float4 == 2MB exactly)
    {
        float4 z = make_float4(0.f, 0.f, 0.f, 0.f);
        ((float4*)out)[(blockIdx.x * 128 + blockIdx.y) * 256 + tid] = z;
    }

    const float4* __restrict__ x4 = (const float4*)(x + row0 * FF);
    const float4* __restrict__ w4 = (const float4*)(wm + obase * FF);
    #pragma unroll
    for (int t = 0; t < 4; t++) {
        int m = tid + 256 * t;          // 1024 float4 per tile
        int r = m >> 4, c4 = m & 15;
        *(float4*)(xs + r * 68 + c4 * 4) = x4[m];
        *(float4*)(ws + r * 68 + c4 * 4) = w4[m];
    }
    __syncthreads();

    const int cx = tid & 15;
    const int ry = tid >> 4;

    ull acc[4][4];
    #pragma unroll
    for (int r = 0; r < 4; r++)
        #pragma unroll
        for (int c = 0; c < 4; c++) acc[r][c] = 0ULL;

    const ulonglong2* __restrict__ xs16 = (const ulonglong2*)xs;
    const ulonglong2* __restrict__ ws16 = (const ulonglong2*)ws;

    #pragma unroll 4
    for (int f4 = 0; f4 < 16; f4++) {
        ulonglong2 xr[4], wv[4];
        #pragma unroll
        for (int r = 0; r < 4; r++) xr[r] = xs16[(ry + 16 * r) * 17 + f4];
        #pragma unroll
        for (int c = 0; c < 4; c++) wv[c] = ws16[(cx + 16 * c) * 17 + f4];
        #pragma unroll
        for (int r = 0; r < 4; r++)
            #pragma unroll
            for (int c = 0; c < 4; c++) {
                acc[r][c] = fma2(xr[r].x, wv[c].x, acc[r][c]);
                acc[r][c] = fma2(xr[r].y, wv[c].y, acc[r][c]);
            }
    }

    float* __restrict__ dst = is_src ? g_fsrc : g_fdst;
    #pragma unroll
    for (int c = 0; c < 4; c++) {
        int oloc = obase + cx + 16 * c;
        float bias = bv[oloc];
        #pragma unroll
        for (int r = 0; r < 4; r++) {
            int bw = row0 + ry + 16 * r;
            dst[bw * CH + oloc] = hsum2(acc[r][c]) + bias;
        }
    }
}

// ---------------------------------------------------------------------------
// Kernel 2: attention, HEAD-SPLIT. grid (8 i-tiles, 64 b, 2 h), 256 threads.
// Each block: one head, 16 destination rows, all 128 source rows in smem.
// Contributes 0.5 * head-sum to out via red.global.add (out pre-zeroed).
// smem (floats):
//   fsrc_h [128 x 64]  swizzled 16B chunks       0 .. 8192
//   fdst_h [16 x 68]   padded                 8192 .. 9280   (reused as red)
//   alpha2 [16 x 128]  DUPLICATED f32 pairs   9280 .. 13376
//   a04    [64]                              13376 .. 13440
//   sA     [128]                             13440 .. 13568  (1.5-prescaled)
//   dA     [16]                              13568 .. 13584
// ---------------------------------------------------------------------------
#define OFF_FDST  8192
#define OFF_ALPHA 9280
#define OFF_A04   13376
#define OFF_SA    13440
#define OFF_DA    13568
#define SM_FLOATS 13584
#define SM_BYTES  (SM_FLOATS * 4)

__global__ __launch_bounds__(256, 4) void attn_kernel(
    const float* __restrict__ attn_w,
    float* __restrict__ out)
{
    extern __shared__ float sm[];
    float* fsrc_sm = sm;
    float* fdst_sm = sm + OFF_FDST;
    ull*   alpha2  = (ull*)(sm + OFF_ALPHA);
    float* a04     = sm + OFF_A04;
    float* sA      = sm + OFF_SA;
    float* dA      = sm + OFF_DA;

    const int tid = threadIdx.x;
    const int b  = blockIdx.y;
    const int i0 = blockIdx.x * TI;
    const int h  = blockIdx.z;

    ulonglong2* fs16 = (ulonglong2*)fsrc_sm;

    // ---- fill fsrc_h: 128 rows x 16 chunks (swizzled, STS.128) ----
    {
        const float4* __restrict__ g4 = (const float4*)(g_fsrc + b * WW * CH + h * 64);
        // row j occupies float4 indices [j*32 + 0 .. 15] of the full-CH layout
        #pragma unroll
        for (int t = 0; t < 8; t++) {
            int m = tid + 256 * t;           // 2048 chunks
            int j = m >> 4, c = m & 15;
            float4 v = g4[j * 32 + c];
            *(float4*)(fsrc_sm + j * 64 + swz16(j, c) * 4) = v;
        }
    }
    // ---- fill fdst_h tile: 16 rows x 16 chunks, padded stride 68 ----
    {
        const float4* __restrict__ g4 = (const float4*)(g_fdst + (b * WW + i0) * CH + h * 64);
        int i = tid >> 4, c = tid & 15;
        *(float4*)(fdst_sm + i * 68 + c * 4) = g4[i * 32 + c];
    }
    if (tid < 64) a04[tid] = 0.4f * attn_w[h * 64 + tid];
    __syncthreads();

    // ---- per-node dots (1.5-prescaled linear leakyrelu component) ----
    if (tid < 128) {               // sA[j]
        int j = tid;
        const ulonglong2* a16 = (const ulonglong2*)a04;
        ull acc = 0ULL;
        #pragma unroll
        for (int f4 = 0; f4 < 16; f4++) {
            ulonglong2 sv = fs16[j * 16 + swz16(j, f4)];
            ulonglong2 av = a16[f4];
            acc = fma2(av.x, sv.x, acc);
            acc = fma2(av.y, sv.y, acc);
        }
        sA[j] = 1.5f * hsum2(acc);
    } else if (tid < 144) {        // dA[i]
        int il = tid - 128;
        const ulonglong2* d16 = (const ulonglong2*)(fdst_sm + il * 68);
        const ulonglong2* a16 = (const ulonglong2*)a04;
        ull acc = 0ULL;
        #pragma unroll
        for (int f4 = 0; f4 < 16; f4++) {
            ulonglong2 dv = d16[f4];
            ulonglong2 av = a16[f4];
            acc = fma2(av.x, dv.x, acc);
            acc = fma2(av.y, dv.y, acc);
        }
        dA[il] = 1.5f * hsum2(acc);
    }
    __syncthreads();

    // ---- score: warp w owns i rows {w, w+8}; lanes jt; j = jt + 32c ----
    const int jt = tid & 31;
    const int w  = tid >> 5;

    ull acc2[2][4];
    #pragma unroll
    for (int r = 0; r < 2; r++)
        #pragma unroll
        for (int c = 0; c < 4; c++) acc2[r][c] = 0ULL;

    {
        const ulonglong2* a16 = (const ulonglong2*)a04;
        #pragma unroll 4
        for (int f4 = 0; f4 < 16; f4++) {
            ulonglong2 av = a16[f4];
            ulonglong2 dv[2], sv[4];
            dv[0] = *(const ulonglong2*)(fdst_sm + w * 68 + f4 * 4);
            dv[1] = *(const ulonglong2*)(fdst_sm + (w + 8) * 68 + f4 * 4);
            int cs = swz16(jt, f4);
            #pragma unroll
            for (int c = 0; c < 4; c++)
                sv[c] = fs16[(jt + 32 * c) * 16 + cs];
            #pragma unroll
            for (int r = 0; r < 2; r++)
                #pragma unroll
                for (int c = 0; c < 4; c++) {
                    ull t0 = add2(sv[c].x, dv[r].x) & ABSMASK;
                    acc2[r][c] = fma2(av.x, t0, acc2[r][c]);
                    ull t1 = add2(sv[c].y, dv[r].y) & ABSMASK;
                    acc2[r][c] = fma2(av.y, t1, acc2[r][c]);
                }
        }
    }

    // ---- softmax over j (in-warp), write DUPLICATED alpha pairs ----
    {
        float sAv[4];
        #pragma unroll
        for (int c = 0; c < 4; c++) sAv[c] = sA[jt + 32 * c];

        #pragma unroll
        for (int r = 0; r < 2; r++) {
            int il = w + 8 * r;
            float dv = dA[il];
            float e[4];
            #pragma unroll
            for (int c = 0; c < 4; c++)
                e[c] = sAv[c] + dv + hsum2(acc2[r][c]);

            float m = fmaxf(fmaxf(e[0], e[1]), fmaxf(e[2], e[3]));
            #pragma unroll
            for (int off = 16; off > 0; off >>= 1)
                m = fmaxf(m, __shfl_xor_sync(0xffffffffu, m, off));

            float p[4], ssum = 0.0f;
            #pragma unroll
            for (int c = 0; c < 4; c++) { p[c] = __expf(e[c] - m); ssum += p[c]; }
            #pragma unroll
            for (int off = 16; off > 0; off >>= 1)
                ssum += __shfl_xor_sync(0xffffffffu, ssum, off);

            float inv = 1.0f / ssum;
            #pragma unroll
            for (int c = 0; c < 4; c++)
                alpha2[il * WW + jt + 32 * c] = dup2(p[c] * inv);
        }
    }
    __syncthreads();

    // ---- aggregation: jh = j-half, r4 -> i rows {r4+4k}, f2 = float pair ----
    const int jh = tid >> 7;
    const int r4 = (tid >> 5) & 3;
    const int f2 = tid & 31;

    ull accA[4];
    #pragma unroll
    for (int k = 0; k < 4; k++) accA[k] = 0ULL;

    {
        const ulonglong2* A2 = (const ulonglong2*)alpha2;   // [row][64 j-pairs]
        const ull* fs8 = (const ull*)fsrc_sm;               // 32 per row
        const int c0 = f2 >> 1;
        const int half = f2 & 1;

        #pragma unroll 4
        for (int jp = 0; jp < 32; jp++) {
            int jp2 = jh * 32 + jp;
            int j0 = 2 * jp2, j1 = j0 + 1;
            ulonglong2 al[4];
            #pragma unroll
            for (int k = 0; k < 4; k++)
                al[k] = A2[(r4 + 4 * k) * 64 + jp2];        // broadcast
            ull s0 = fs8[j0 * 32 + swz16(j0, c0) * 2 + half];
            ull s1 = fs8[j1 * 32 + swz16(j1, c0) * 2 + half];
            #pragma unroll
            for (int k = 0; k < 4; k++) {
                accA[k] = fma2(al[k].x, s0, accA[k]);
                accA[k] = fma2(al[k].y, s1, accA[k]);
            }
        }
    }

    // ---- cross-half reduction + atomic add into out ----
    __syncthreads();
    {
        ull* red = (ull*)fdst_sm;            // 128 x 4 ull = 4KB scratch
        if (jh == 1) {
            int base = (tid & 127) * 4;
            #pragma unroll
            for (int k = 0; k < 4; k++) red[base + k] = accA[k];
        }
        __syncthreads();
        if (jh == 0) {
            const ull* rr = red + tid * 4;
            #pragma unroll
            for (int k = 0; k < 4; k++) {
                ull s = add2(accA[k], rr[k]);
                int i = i0 + r4 + 4 * k;
                float* op = out + (b * WW + i) * OUTF + f2 * 2;
                atomicAdd(op,     0.5f * lo2(s));
                atomicAdd(op + 1, 0.5f * hi2(s));
            }
        }
    }
}

// ---------------------------------------------------------------------------
extern "C" void kernel_launch(void* const* d_in, const int* in_sizes, int n_in,
                              void* d_out, int out_size)
{
    (void)in_sizes; (void)n_in; (void)out_size;
    const float* x      = (const float*)d_in[0];
    const float* w_src  = (const float*)d_in[1];
    const float* b_src  = (const float*)d_in[2];
    const float* w_dst  = (const float*)d_in[3];
    const float* b_dst  = (const float*)d_in[4];
    const float* attn_w = (const float*)d_in[5];
    float* out = (float*)d_out;

    cudaFuncSetAttribute(attn_kernel,
                         cudaFuncAttributeMaxDynamicSharedMemorySize,
                         SM_BYTES);

    proj_kernel<<<dim3(4, 128), 256>>>(x, w_src, b_src, w_dst, b_dst, out);
    attn_kernel<<<dim3(WW / TI, BB, 2), 256, SM_BYTES>>>(attn_w, out);
}